// round 9
// baseline (speedup 1.0000x reference)
#include <cuda_runtime.h>
#include <cuda_fp16.h>
#include <cstdint>
#include <math.h>

// ---------------- problem constants ----------------
#define M_TOK   8192
#define IN_F    2048
#define OUT_F   2048
#define NEXP    4
#define RANK    8
#define NJ      32
#define SCALE   2.0f

// extended-K layout: [x fp16 (2048) | coef fp16 (32) | zero pad (32)]
#define KLORA0  2048
#define KEXT    2112            // 33 tiles of 64

// ---------------- device scratch (static, no allocation) ----------------
__device__ __align__(128) __half g_Aext[(size_t)M_TOK * KEXT];
__device__ __align__(128) __half g_Bext[(size_t)OUT_F * KEXT];
__device__ __align__(128) __half g_Wr[64 * IN_F];

// ---------------- helpers ----------------
__device__ __forceinline__ uint32_t smem_u32(const void* p) {
    uint32_t a;
    asm("{ .reg .u64 t; cvta.to.shared.u64 t, %1; cvt.u32.u64 %0, t; }" : "=r"(a) : "l"(p));
    return a;
}
__device__ __forceinline__ uint32_t sw128(uint32_t off) { return off ^ ((off >> 3) & 0x70); }
__device__ __forceinline__ void cp_async16(uint32_t dst, const void* src) {
    asm volatile("cp.async.cg.shared.global [%0], [%1], 16;" :: "r"(dst), "l"(src) : "memory");
}
__device__ __forceinline__ void cp_commit() {
    asm volatile("cp.async.commit_group;" ::: "memory");
}
__device__ __forceinline__ void ldsm4(uint32_t* r, uint32_t addr) {
    asm volatile("ldmatrix.sync.aligned.m8n8.x4.shared.b16 {%0,%1,%2,%3}, [%4];"
                 : "=r"(r[0]), "=r"(r[1]), "=r"(r[2]), "=r"(r[3]) : "r"(addr));
}
__device__ __forceinline__ void mma_fp16(float* c, const uint32_t* a, uint32_t b0, uint32_t b1) {
    asm volatile("mma.sync.aligned.m16n8k16.row.col.f32.f16.f16.f32 "
                 "{%0,%1,%2,%3}, {%4,%5,%6,%7}, {%8,%9}, {%0,%1,%2,%3};"
                 : "+f"(c[0]), "+f"(c[1]), "+f"(c[2]), "+f"(c[3])
                 : "r"(a[0]), "r"(a[1]), "r"(a[2]), "r"(a[3]), "r"(b0), "r"(b1));
}
// fp16-accumulate variant: D,C are 2x b32 (4 halves)
__device__ __forceinline__ void mma_fp16_hacc(uint32_t* c, const uint32_t* a, uint32_t b0, uint32_t b1) {
    asm volatile("mma.sync.aligned.m16n8k16.row.col.f16.f16.f16.f16 "
                 "{%0,%1}, {%2,%3,%4,%5}, {%6,%7}, {%0,%1};"
                 : "+r"(c[0]), "+r"(c[1])
                 : "r"(a[0]), "r"(a[1]), "r"(a[2]), "r"(a[3]), "r"(b0), "r"(b1));
}

// ---------------- Kernel: X -> A_ext fp16 ----------------
__global__ __launch_bounds__(256)
void convert_x_kernel(const float* __restrict__ X, __half* __restrict__ Aext)
{
    int i = blockIdx.x * 256 + threadIdx.x;
    const int GPR = IN_F / 4;
    int m  = i / GPR;
    int k4 = (i - m * GPR) * 4;
    float4 v = *(const float4*)(X + (size_t)m * IN_F + k4);
    __half2 h01 = __floats2half2_rn(v.x, v.y);
    __half2 h23 = __floats2half2_rn(v.z, v.w);
    size_t base = (size_t)m * KEXT + k4;
    *(__half2*)(Aext + base)     = h01;
    *(__half2*)(Aext + base + 2) = h23;
}

// ---------------- Kernel: W -> B_ext fp16, fused Bcat tail + zero-pad ----------------
__global__ __launch_bounds__(256)
void convert_w_bcat_kernel(const float* __restrict__ W, const float* __restrict__ Bm,
                           __half* __restrict__ Bext)
{
    int i = blockIdx.x * 256 + threadIdx.x;
    const int MAIN = OUT_F * (IN_F / 4);
    if (i < MAIN) {
        int n  = i >> 9;
        int k4 = (i & 511) * 4;
        float4 v = *(const float4*)(W + (size_t)n * IN_F + k4);
        __half2 h01 = __floats2half2_rn(v.x, v.y);
        __half2 h23 = __floats2half2_rn(v.z, v.w);
        size_t base = (size_t)n * KEXT + k4;
        *(__half2*)(Bext + base)     = h01;
        *(__half2*)(Bext + base + 2) = h23;
        return;
    }
    i -= MAIN;
    int n = i >> 6, j = i & 63;
    float b = 0.0f;
    if (j < NJ) {
        int e = j >> 3, r = j & 7;
        b = Bm[((size_t)e * OUT_F + n) * RANK + r];
    }
    Bext[(size_t)n * KEXT + KLORA0 + j] = __float2half_rn(b);
}

// ---------------- Kernel: pack [A(32) | Rw(4) | zeros(28)] -> Wr fp16 ----------------
__global__ __launch_bounds__(256)
void wr_pack_kernel(const float* __restrict__ A, const float* __restrict__ Rw,
                    __half* __restrict__ Wr)
{
    int i = blockIdx.x * 256 + threadIdx.x;
    int row = i >> 9;
    int k4  = (i & 511) * 4;
    float4 v = make_float4(0.f, 0.f, 0.f, 0.f);
    if (row < 32)      v = *(const float4*)(A  + (size_t)row * IN_F + k4);
    else if (row < 36) v = *(const float4*)(Rw + (size_t)(row - 32) * IN_F + k4);
    __half2 h01 = __floats2half2_rn(v.x, v.y);
    __half2 h23 = __floats2half2_rn(v.z, v.w);
    size_t base = (size_t)row * IN_F + k4;
    *(__half2*)(Wr + base)     = h01;
    *(__half2*)(Wr + base + 2) = h23;
}

// ---------------- Router GEMM (validated) ----------------
#define RT_NKT (IN_F / 64)

__global__ __launch_bounds__(128, 2)
void router_gemm_kernel(const __half* __restrict__ Aext,
                        const __half* __restrict__ Wr,
                        __half* __restrict__ AextW)
{
    __shared__ __align__(128) char smem[2 * 16384];
    const uint32_t s0 = smem_u32(smem);
    const int tid = threadIdx.x;
    const int w = tid >> 5, lane = tid & 31;
    const int m0 = blockIdx.x * 64;

    const int lrow = tid >> 3;
    const int lch  = tid & 7;
    uint32_t dstA[4], dstB[4];
    const __half* srcA[4]; const __half* srcB[4];
#pragma unroll
    for (int r = 0; r < 4; r++) {
        int row = lrow + 16 * r;
        dstA[r] = sw128(row * 128 + lch * 16);
        dstB[r] = 8192 + sw128(row * 128 + lch * 16);
        srcA[r] = Aext + (size_t)(m0 + row) * KEXT + lch * 8;
        srcB[r] = Wr + (size_t)row * IN_F + lch * 8;
    }

    auto load_tile = [&](int kt, int s) {
        const uint32_t base = s0 + s * 16384;
        const int ko = kt * 64;
#pragma unroll
        for (int r = 0; r < 4; r++) {
            cp_async16(base + dstA[r], srcA[r] + ko);
            cp_async16(base + dstB[r], srcB[r] + ko);
        }
        cp_commit();
    };

    float acc[8][4];
#pragma unroll
    for (int j = 0; j < 8; j++)
#pragma unroll
        for (int k = 0; k < 4; k++) acc[j][k] = 0.0f;

    load_tile(0, 0);
    load_tile(1, 1);

    const int arow = w * 16 + (lane & 15);
    const int brow = lane & 15;
    const int chsel = lane >> 4;

    for (int kt = 0; kt < RT_NKT; kt++) {
        const int s = kt & 1;
        if (kt + 1 < RT_NKT) asm volatile("cp.async.wait_group 1;" ::: "memory");
        else                 asm volatile("cp.async.wait_group 0;" ::: "memory");
        __syncthreads();

        const uint32_t base = s0 + s * 16384;
#pragma unroll
        for (int ks = 0; ks < 4; ks++) {
            const int ch = ks * 2 + chsel;
            uint32_t a[4];
            ldsm4(a, base + sw128(arow * 128 + ch * 16));
            uint32_t b[4][4];
#pragma unroll
            for (int q = 0; q < 4; q++)
                ldsm4(b[q], base + 8192 + sw128((q * 16 + brow) * 128 + ch * 16));
#pragma unroll
            for (int q = 0; q < 4; q++) {
                mma_fp16(acc[2*q],   a, b[q][0], b[q][2]);
                mma_fp16(acc[2*q+1], a, b[q][1], b[q][3]);
            }
        }
        __syncthreads();
        if (kt + 2 < RT_NKT) load_tile(kt + 2, s);
    }

    const int qbase = lane & ~3;
    float La0 = __shfl_sync(0xffffffffu, acc[4][0], qbase);
    float La1 = __shfl_sync(0xffffffffu, acc[4][1], qbase);
    float Lb0 = __shfl_sync(0xffffffffu, acc[4][0], qbase | 1);
    float Lb1 = __shfl_sync(0xffffffffu, acc[4][1], qbase | 1);
    float Ma0 = __shfl_sync(0xffffffffu, acc[4][2], qbase);
    float Ma1 = __shfl_sync(0xffffffffu, acc[4][3], qbase);
    float Mb0 = __shfl_sync(0xffffffffu, acc[4][2], qbase | 1);
    float Mb1 = __shfl_sync(0xffffffffu, acc[4][3], qbase | 1);

    float g1[4], g2[4];
    {
        float mx = fmaxf(fmaxf(La0, La1), fmaxf(Lb0, Lb1));
        float e0 = __expf(La0 - mx), e1 = __expf(La1 - mx),
              e2 = __expf(Lb0 - mx), e3 = __expf(Lb1 - mx);
        float s = SCALE / (e0 + e1 + e2 + e3);
        g1[0] = e0 * s; g1[1] = e1 * s; g1[2] = e2 * s; g1[3] = e3 * s;
    }
    {
        float mx = fmaxf(fmaxf(Ma0, Ma1), fmaxf(Mb0, Mb1));
        float e0 = __expf(Ma0 - mx), e1 = __expf(Ma1 - mx),
              e2 = __expf(Mb0 - mx), e3 = __expf(Mb1 - mx);
        float s = SCALE / (e0 + e1 + e2 + e3);
        g2[0] = e0 * s; g2[1] = e1 * s; g2[2] = e2 * s; g2[3] = e3 * s;
    }

    const int t1 = m0 + w * 16 + (lane >> 2);
    const int t2 = t1 + 8;
    __half* tail1 = AextW + (size_t)t1 * KEXT + KLORA0;
    __half* tail2 = AextW + (size_t)t2 * KEXT + KLORA0;
    const int jq = (lane & 3) * 2;
#pragma unroll
    for (int nf = 0; nf < 4; nf++) {
        int j = nf * 8 + jq;
        *(__half2*)(tail1 + j) = __floats2half2_rn(acc[nf][0] * g1[nf], acc[nf][1] * g1[nf]);
        *(__half2*)(tail2 + j) = __floats2half2_rn(acc[nf][2] * g2[nf], acc[nf][3] * g2[nf]);
    }
    __half2 z; z.x = __float2half_rn(0.f); z.y = z.x;
#pragma unroll
    for (int nf = 4; nf < 8; nf++) {
        int j = nf * 8 + jq;
        *(__half2*)(tail1 + j) = z;
        *(__half2*)(tail2 + j) = z;
    }
}

// ---------------- Main GEMM: 128x128x64, 4 warps of 64x64, 3-stage,
// ---------------- fp16 accumulate + fp32 promotion every 2 k-tiles ----------------
#define BMg 128
#define BNg 128
#define BKg 64
#define A_BYTES 16384
#define STAGE_BYTES 32768
#define NSTAGE 3
#define GEMM_SMEM (NSTAGE * STAGE_BYTES)
#define NKTg (KEXT / BKg)                   // 33

__global__ __launch_bounds__(128, 2)
void gemm_hmma_kernel(const __half* __restrict__ Aext,
                      const __half* __restrict__ Bext,
                      const float* __restrict__ bias,
                      float* __restrict__ out)
{
    extern __shared__ __align__(128) char smem[];
    const uint32_t s0 = smem_u32(smem);
    const int tid  = threadIdx.x;
    const int wid  = tid >> 5, lane = tid & 31;
    const int wm   = wid & 1, wn = wid >> 1;
    const int m0   = blockIdx.y * BMg, n0 = blockIdx.x * BNg;

    const int lrow = tid >> 3;
    const int lch  = tid & 7;
    uint32_t dstA[8], dstB[8];
    const __half* srcA = Aext + (size_t)(m0 + lrow) * KEXT + lch * 8;
    const __half* srcB = Bext + (size_t)(n0 + lrow) * KEXT + lch * 8;
#pragma unroll
    for (int r = 0; r < 8; r++) {
        dstA[r] = sw128((lrow + 16 * r) * 128 + lch * 16);
        dstB[r] = A_BYTES + sw128((lrow + 16 * r) * 128 + lch * 16);
    }

    auto load_tile = [&](int kt, int s) {
        const uint32_t base = s0 + s * STAGE_BYTES;
        const int ko = kt * BKg;
#pragma unroll
        for (int r = 0; r < 8; r++) {
            cp_async16(base + dstA[r], srcA + (size_t)(16 * r) * KEXT + ko);
            cp_async16(base + dstB[r], srcB + (size_t)(16 * r) * KEXT + ko);
        }
        cp_commit();
    };

    float accf[4][8][4];
    uint32_t acch[4][8][2];
#pragma unroll
    for (int i = 0; i < 4; i++)
#pragma unroll
        for (int j = 0; j < 8; j++) {
#pragma unroll
            for (int k = 0; k < 4; k++) accf[i][j][k] = 0.0f;
            acch[i][j][0] = 0u; acch[i][j][1] = 0u;
        }

    load_tile(0, 0);
    load_tile(1, 1);

    const int arow = wm * 64 + (lane & 15);
    const int brow = wn * 64 + (lane & 15);
    const int chsel = lane >> 4;

    for (int kt = 0; kt < NKTg; kt++) {
        if (kt + 1 < NKTg) asm volatile("cp.async.wait_group 1;" ::: "memory");
        else               asm volatile("cp.async.wait_group 0;" ::: "memory");
        __syncthreads();
        if (kt + 2 < NKTg) load_tile(kt + 2, (kt + 2) % NSTAGE);

        const uint32_t base = s0 + (kt % NSTAGE) * STAGE_BYTES;
#pragma unroll
        for (int ks = 0; ks < 4; ks++) {
            const int ch = ks * 2 + chsel;
            uint32_t a[4][4], b[4][4];
#pragma unroll
            for (int q = 0; q < 4; q++)
                ldsm4(a[q], base + sw128((arow + q * 16) * 128 + ch * 16));
#pragma unroll
            for (int q = 0; q < 4; q++)
                ldsm4(b[q], base + A_BYTES + sw128((brow + q * 16) * 128 + ch * 16));
#pragma unroll
            for (int i = 0; i < 4; i++)
#pragma unroll
                for (int q = 0; q < 4; q++) {
                    mma_fp16_hacc(acch[i][2*q],   a[i], b[q][0], b[q][2]);
                    mma_fp16_hacc(acch[i][2*q+1], a[i], b[q][1], b[q][3]);
                }
        }

        // promote fp16 partials to fp32 every 2 k-tiles (K=128) and at the end
        if ((kt & 1) || (kt == NKTg - 1)) {
#pragma unroll
            for (int i = 0; i < 4; i++)
#pragma unroll
                for (int j = 0; j < 8; j++) {
                    float2 f0 = __half22float2(*(__half2*)&acch[i][j][0]);
                    float2 f1 = __half22float2(*(__half2*)&acch[i][j][1]);
                    accf[i][j][0] += f0.x; accf[i][j][1] += f0.y;
                    accf[i][j][2] += f1.x; accf[i][j][3] += f1.y;
                    acch[i][j][0] = 0u; acch[i][j][1] = 0u;
                }
        }
    }

    // epilogue: + bias
#pragma unroll
    for (int mf = 0; mf < 4; mf++) {
        const int row = m0 + wm * 64 + mf * 16 + (lane >> 2);
#pragma unroll
        for (int nf = 0; nf < 8; nf++) {
            const int col = n0 + wn * 64 + nf * 8 + (lane & 3) * 2;
            float2 bv = *(const float2*)(bias + col);
            float2 o0, o1;
            o0.x = accf[mf][nf][0] + bv.x; o0.y = accf[mf][nf][1] + bv.y;
            o1.x = accf[mf][nf][2] + bv.x; o1.y = accf[mf][nf][3] + bv.y;
            *(float2*)(out + (size_t)row * OUT_F + col)       = o0;
            *(float2*)(out + (size_t)(row + 8) * OUT_F + col) = o1;
        }
    }
}

// ---------------- host launcher (multi-stream graph fork) ----------------
extern "C" void kernel_launch(void* const* d_in, const int* in_sizes, int n_in,
                              void* d_out, int out_size)
{
    const float* x      = (const float*)d_in[0];
    const float* base_w = (const float*)d_in[1];
    const float* base_b = (const float*)d_in[2];
    const float* A      = (const float*)d_in[3];
    const float* Bm     = (const float*)d_in[4];
    const float* rw     = (const float*)d_in[5];
    float* out = (float*)d_out;

    __half *Aext = nullptr, *Bext = nullptr, *Wr = nullptr;
    cudaGetSymbolAddress((void**)&Aext, g_Aext);
    cudaGetSymbolAddress((void**)&Bext, g_Bext);
    cudaGetSymbolAddress((void**)&Wr,   g_Wr);

    static bool init_done = false;
    static cudaStream_t s1;
    static cudaEvent_t evFork, evJoin;
    if (!init_done) {
        cudaFuncSetAttribute(gemm_hmma_kernel,
                             cudaFuncAttributeMaxDynamicSharedMemorySize, GEMM_SMEM);
        cudaStreamCreateWithFlags(&s1, cudaStreamNonBlocking);
        cudaEventCreateWithFlags(&evFork, cudaEventDisableTiming);
        cudaEventCreateWithFlags(&evJoin, cudaEventDisableTiming);
        init_done = true;
    }

    // fork: B-side conversion on s1, concurrent with X-side + router on stream 0
    cudaEventRecord(evFork, 0);
    cudaStreamWaitEvent(s1, evFork, 0);
    {
        int total = OUT_F * (IN_F / 4) + OUT_F * 64;
        convert_w_bcat_kernel<<<(total + 255) / 256, 256, 0, s1>>>(base_w, Bm, Bext);
    }
    cudaEventRecord(evJoin, s1);

    convert_x_kernel<<<(M_TOK * IN_F / 4) / 256, 256>>>(x, Aext);
    wr_pack_kernel<<<(64 * IN_F / 4) / 256, 256>>>(A, rw, Wr);
    router_gemm_kernel<<<M_TOK / 64, 128>>>(Aext, Wr, Aext);

    cudaStreamWaitEvent(0, evJoin, 0);
    dim3 grid(OUT_F / BNg, M_TOK / BMg);   // (16, 64)
    gemm_hmma_kernel<<<grid, 128, GEMM_SMEM>>>(Aext, Bext, base_b, out);
}

// round 10
// speedup vs baseline: 1.1538x; 1.1538x over previous
#include <cuda_runtime.h>
#include <cuda_fp16.h>
#include <cstdint>
#include <math.h>

// ---------------- problem constants ----------------
#define M_TOK   8192
#define IN_F    2048
#define OUT_F   2048
#define NEXP    4
#define RANK    8
#define NJ      32
#define SCALE   2.0f

// extended-K layout: [x fp16 (2048) | coef fp16 (32) | zero pad (32)]
#define KLORA0  2048
#define KEXT    2112            // 33 tiles of 64

// ---------------- device scratch (static, no allocation) ----------------
__device__ __align__(128) __half g_Aext[(size_t)M_TOK * KEXT];
__device__ __align__(128) __half g_Bext[(size_t)OUT_F * KEXT];
__device__ __align__(128) __half g_Wr[64 * IN_F];

// ---------------- helpers ----------------
__device__ __forceinline__ uint32_t smem_u32(const void* p) {
    uint32_t a;
    asm("{ .reg .u64 t; cvta.to.shared.u64 t, %1; cvt.u32.u64 %0, t; }" : "=r"(a) : "l"(p));
    return a;
}
__device__ __forceinline__ uint32_t sw128(uint32_t off) { return off ^ ((off >> 3) & 0x70); }
__device__ __forceinline__ void cp_async16(uint32_t dst, const void* src) {
    asm volatile("cp.async.cg.shared.global [%0], [%1], 16;" :: "r"(dst), "l"(src) : "memory");
}
__device__ __forceinline__ void cp_commit() {
    asm volatile("cp.async.commit_group;" ::: "memory");
}
__device__ __forceinline__ void ldsm4(uint32_t* r, uint32_t addr) {
    asm volatile("ldmatrix.sync.aligned.m8n8.x4.shared.b16 {%0,%1,%2,%3}, [%4];"
                 : "=r"(r[0]), "=r"(r[1]), "=r"(r[2]), "=r"(r[3]) : "r"(addr));
}
__device__ __forceinline__ void mma_fp16(float* c, const uint32_t* a, uint32_t b0, uint32_t b1) {
    asm volatile("mma.sync.aligned.m16n8k16.row.col.f32.f16.f16.f32 "
                 "{%0,%1,%2,%3}, {%4,%5,%6,%7}, {%8,%9}, {%0,%1,%2,%3};"
                 : "+f"(c[0]), "+f"(c[1]), "+f"(c[2]), "+f"(c[3])
                 : "r"(a[0]), "r"(a[1]), "r"(a[2]), "r"(a[3]), "r"(b0), "r"(b1));
}

// ---------------- Kernel: X -> A_ext fp16 ----------------
__global__ __launch_bounds__(256)
void convert_x_kernel(const float* __restrict__ X, __half* __restrict__ Aext)
{
    int i = blockIdx.x * 256 + threadIdx.x;
    const int GPR = IN_F / 4;
    int m  = i / GPR;
    int k4 = (i - m * GPR) * 4;
    float4 v = *(const float4*)(X + (size_t)m * IN_F + k4);
    __half2 h01 = __floats2half2_rn(v.x, v.y);
    __half2 h23 = __floats2half2_rn(v.z, v.w);
    size_t base = (size_t)m * KEXT + k4;
    *(__half2*)(Aext + base)     = h01;
    *(__half2*)(Aext + base + 2) = h23;
}

// ---------------- Kernel: W -> B_ext fp16, fused Bcat tail + zero-pad ----------------
__global__ __launch_bounds__(256)
void convert_w_bcat_kernel(const float* __restrict__ W, const float* __restrict__ Bm,
                           __half* __restrict__ Bext)
{
    int i = blockIdx.x * 256 + threadIdx.x;
    const int MAIN = OUT_F * (IN_F / 4);
    if (i < MAIN) {
        int n  = i >> 9;
        int k4 = (i & 511) * 4;
        float4 v = *(const float4*)(W + (size_t)n * IN_F + k4);
        __half2 h01 = __floats2half2_rn(v.x, v.y);
        __half2 h23 = __floats2half2_rn(v.z, v.w);
        size_t base = (size_t)n * KEXT + k4;
        *(__half2*)(Bext + base)     = h01;
        *(__half2*)(Bext + base + 2) = h23;
        return;
    }
    i -= MAIN;
    int n = i >> 6, j = i & 63;
    float b = 0.0f;
    if (j < NJ) {
        int e = j >> 3, r = j & 7;
        b = Bm[((size_t)e * OUT_F + n) * RANK + r];
    }
    Bext[(size_t)n * KEXT + KLORA0 + j] = __float2half_rn(b);
}

// ---------------- Kernel: pack [A(32) | Rw(4) | zeros(28)] -> Wr fp16 ----------------
__global__ __launch_bounds__(256)
void wr_pack_kernel(const float* __restrict__ A, const float* __restrict__ Rw,
                    __half* __restrict__ Wr)
{
    int i = blockIdx.x * 256 + threadIdx.x;
    int row = i >> 9;
    int k4  = (i & 511) * 4;
    float4 v = make_float4(0.f, 0.f, 0.f, 0.f);
    if (row < 32)      v = *(const float4*)(A  + (size_t)row * IN_F + k4);
    else if (row < 36) v = *(const float4*)(Rw + (size_t)(row - 32) * IN_F + k4);
    __half2 h01 = __floats2half2_rn(v.x, v.y);
    __half2 h23 = __floats2half2_rn(v.z, v.w);
    size_t base = (size_t)row * IN_F + k4;
    *(__half2*)(Wr + base)     = h01;
    *(__half2*)(Wr + base + 2) = h23;
}

// ---------------- Router GEMM (validated at R5) ----------------
#define RT_NKT (IN_F / 64)

__global__ __launch_bounds__(128, 2)
void router_gemm_kernel(const __half* __restrict__ Aext,
                        const __half* __restrict__ Wr,
                        __half* __restrict__ AextW)
{
    __shared__ __align__(128) char smem[2 * 16384];
    const uint32_t s0 = smem_u32(smem);
    const int tid = threadIdx.x;
    const int w = tid >> 5, lane = tid & 31;
    const int m0 = blockIdx.x * 64;

    const int lrow = tid >> 3;
    const int lch  = tid & 7;
    uint32_t dstA[4], dstB[4];
    const __half* srcA[4]; const __half* srcB[4];
#pragma unroll
    for (int r = 0; r < 4; r++) {
        int row = lrow + 16 * r;
        dstA[r] = sw128(row * 128 + lch * 16);
        dstB[r] = 8192 + sw128(row * 128 + lch * 16);
        srcA[r] = Aext + (size_t)(m0 + row) * KEXT + lch * 8;
        srcB[r] = Wr + (size_t)row * IN_F + lch * 8;
    }

    auto load_tile = [&](int kt, int s) {
        const uint32_t base = s0 + s * 16384;
        const int ko = kt * 64;
#pragma unroll
        for (int r = 0; r < 4; r++) {
            cp_async16(base + dstA[r], srcA[r] + ko);
            cp_async16(base + dstB[r], srcB[r] + ko);
        }
        cp_commit();
    };

    float acc[8][4];
#pragma unroll
    for (int j = 0; j < 8; j++)
#pragma unroll
        for (int k = 0; k < 4; k++) acc[j][k] = 0.0f;

    load_tile(0, 0);
    load_tile(1, 1);

    const int arow = w * 16 + (lane & 15);
    const int brow = lane & 15;
    const int chsel = lane >> 4;

    for (int kt = 0; kt < RT_NKT; kt++) {
        const int s = kt & 1;
        if (kt + 1 < RT_NKT) asm volatile("cp.async.wait_group 1;" ::: "memory");
        else                 asm volatile("cp.async.wait_group 0;" ::: "memory");
        __syncthreads();

        const uint32_t base = s0 + s * 16384;
#pragma unroll
        for (int ks = 0; ks < 4; ks++) {
            const int ch = ks * 2 + chsel;
            uint32_t a[4];
            ldsm4(a, base + sw128(arow * 128 + ch * 16));
            uint32_t b[4][4];
#pragma unroll
            for (int q = 0; q < 4; q++)
                ldsm4(b[q], base + 8192 + sw128((q * 16 + brow) * 128 + ch * 16));
#pragma unroll
            for (int q = 0; q < 4; q++) {
                mma_fp16(acc[2*q],   a, b[q][0], b[q][2]);
                mma_fp16(acc[2*q+1], a, b[q][1], b[q][3]);
            }
        }
        __syncthreads();
        if (kt + 2 < RT_NKT) load_tile(kt + 2, s);
    }

    const int qbase = lane & ~3;
    float La0 = __shfl_sync(0xffffffffu, acc[4][0], qbase);
    float La1 = __shfl_sync(0xffffffffu, acc[4][1], qbase);
    float Lb0 = __shfl_sync(0xffffffffu, acc[4][0], qbase | 1);
    float Lb1 = __shfl_sync(0xffffffffu, acc[4][1], qbase | 1);
    float Ma0 = __shfl_sync(0xffffffffu, acc[4][2], qbase);
    float Ma1 = __shfl_sync(0xffffffffu, acc[4][3], qbase);
    float Mb0 = __shfl_sync(0xffffffffu, acc[4][2], qbase | 1);
    float Mb1 = __shfl_sync(0xffffffffu, acc[4][3], qbase | 1);

    float g1[4], g2[4];
    {
        float mx = fmaxf(fmaxf(La0, La1), fmaxf(Lb0, Lb1));
        float e0 = __expf(La0 - mx), e1 = __expf(La1 - mx),
              e2 = __expf(Lb0 - mx), e3 = __expf(Lb1 - mx);
        float s = SCALE / (e0 + e1 + e2 + e3);
        g1[0] = e0 * s; g1[1] = e1 * s; g1[2] = e2 * s; g1[3] = e3 * s;
    }
    {
        float mx = fmaxf(fmaxf(Ma0, Ma1), fmaxf(Mb0, Mb1));
        float e0 = __expf(Ma0 - mx), e1 = __expf(Ma1 - mx),
              e2 = __expf(Mb0 - mx), e3 = __expf(Mb1 - mx);
        float s = SCALE / (e0 + e1 + e2 + e3);
        g2[0] = e0 * s; g2[1] = e1 * s; g2[2] = e2 * s; g2[3] = e3 * s;
    }

    const int t1 = m0 + w * 16 + (lane >> 2);
    const int t2 = t1 + 8;
    __half* tail1 = AextW + (size_t)t1 * KEXT + KLORA0;
    __half* tail2 = AextW + (size_t)t2 * KEXT + KLORA0;
    const int jq = (lane & 3) * 2;
#pragma unroll
    for (int nf = 0; nf < 4; nf++) {
        int j = nf * 8 + jq;
        *(__half2*)(tail1 + j) = __floats2half2_rn(acc[nf][0] * g1[nf], acc[nf][1] * g1[nf]);
        *(__half2*)(tail2 + j) = __floats2half2_rn(acc[nf][2] * g2[nf], acc[nf][3] * g2[nf]);
    }
    __half2 z; z.x = __float2half_rn(0.f); z.y = z.x;
#pragma unroll
    for (int nf = 4; nf < 8; nf++) {
        int j = nf * 8 + jq;
        *(__half2*)(tail1 + j) = z;
        *(__half2*)(tail2 + j) = z;
    }
}

// ---------------- Main GEMM: R5 config (best measured) ----------------
// 128x128x64, 256 threads, 8 warps of 32x64, 2-stage, SW128, 2 CTA/SM
#define BMg 128
#define BNg 128
#define BKg 64
#define A_BYTES 16384
#define STAGE_BYTES 32768
#define GEMM_SMEM (2 * STAGE_BYTES)       // 65536
#define NKTg (KEXT / BKg)                 // 33

__global__ __launch_bounds__(256, 2)
void gemm_hmma_kernel(const __half* __restrict__ Aext,
                      const __half* __restrict__ Bext,
                      const float* __restrict__ bias,
                      float* __restrict__ out)
{
    extern __shared__ __align__(128) char smem[];
    const uint32_t s0 = smem_u32(smem);
    const int tid  = threadIdx.x;
    const int wid  = tid >> 5, lane = tid & 31;
    const int wm   = wid >> 1, wn = wid & 1;       // 4x2 grid, 32x64 warp tiles
    const int m0   = blockIdx.y * BMg, n0 = blockIdx.x * BNg;

    const int lrow = tid >> 3;       // 0..31
    const int lch  = tid & 7;
    uint32_t dstA[4], dstB[4];
    const __half* srcA[4]; const __half* srcB[4];
#pragma unroll
    for (int r = 0; r < 4; r++) {
        int row = lrow + 32 * r;
        dstA[r] = sw128(row * 128 + lch * 16);
        dstB[r] = A_BYTES + sw128(row * 128 + lch * 16);
        srcA[r] = Aext + (size_t)(m0 + row) * KEXT + lch * 8;
        srcB[r] = Bext + (size_t)(n0 + row) * KEXT + lch * 8;
    }

    auto load_tile = [&](int kt, int s) {
        const uint32_t base = s0 + s * STAGE_BYTES;
        const int ko = kt * BKg;
#pragma unroll
        for (int r = 0; r < 4; r++) {
            cp_async16(base + dstA[r], srcA[r] + ko);
            cp_async16(base + dstB[r], srcB[r] + ko);
        }
        cp_commit();
    };

    float acc[2][8][4];
#pragma unroll
    for (int i = 0; i < 2; i++)
#pragma unroll
        for (int j = 0; j < 8; j++)
#pragma unroll
            for (int k = 0; k < 4; k++) acc[i][j][k] = 0.0f;

    load_tile(0, 0);
    load_tile(1, 1);

    const int arow0 = wm * 32 + (lane & 15);
    const int brow  = wn * 64 + (lane & 15);
    const int chsel = lane >> 4;

    for (int kt = 0; kt < NKTg; kt++) {
        const int s = kt & 1;
        if (kt + 1 < NKTg) asm volatile("cp.async.wait_group 1;" ::: "memory");
        else               asm volatile("cp.async.wait_group 0;" ::: "memory");
        __syncthreads();

        const uint32_t base = s0 + s * STAGE_BYTES;
#pragma unroll
        for (int ks = 0; ks < 4; ks++) {
            const int ch = ks * 2 + chsel;
            uint32_t a0[4], a1[4];
            ldsm4(a0, base + sw128(arow0 * 128 + ch * 16));
            ldsm4(a1, base + sw128((arow0 + 16) * 128 + ch * 16));
            uint32_t b[4][4];
#pragma unroll
            for (int q = 0; q < 4; q++)
                ldsm4(b[q], base + A_BYTES + sw128((brow + q * 16) * 128 + ch * 16));
#pragma unroll
            for (int q = 0; q < 4; q++) {
                mma_fp16(acc[0][2*q],   a0, b[q][0], b[q][2]);
                mma_fp16(acc[0][2*q+1], a0, b[q][1], b[q][3]);
                mma_fp16(acc[1][2*q],   a1, b[q][0], b[q][2]);
                mma_fp16(acc[1][2*q+1], a1, b[q][1], b[q][3]);
            }
        }
        __syncthreads();
        if (kt + 2 < NKTg) load_tile(kt + 2, s);
    }

    // epilogue: + bias
#pragma unroll
    for (int mf = 0; mf < 2; mf++) {
        const int row = m0 + wm * 32 + mf * 16 + (lane >> 2);
#pragma unroll
        for (int nf = 0; nf < 8; nf++) {
            const int col = n0 + wn * 64 + nf * 8 + (lane & 3) * 2;
            float2 bv = *(const float2*)(bias + col);
            float2 o0, o1;
            o0.x = acc[mf][nf][0] + bv.x; o0.y = acc[mf][nf][1] + bv.y;
            o1.x = acc[mf][nf][2] + bv.x; o1.y = acc[mf][nf][3] + bv.y;
            *(float2*)(out + (size_t)row * OUT_F + col)       = o0;
            *(float2*)(out + (size_t)(row + 8) * OUT_F + col) = o1;
        }
    }
}

// ---------------- host launcher (multi-stream graph fork) ----------------
extern "C" void kernel_launch(void* const* d_in, const int* in_sizes, int n_in,
                              void* d_out, int out_size)
{
    const float* x      = (const float*)d_in[0];
    const float* base_w = (const float*)d_in[1];
    const float* base_b = (const float*)d_in[2];
    const float* A      = (const float*)d_in[3];
    const float* Bm     = (const float*)d_in[4];
    const float* rw     = (const float*)d_in[5];
    float* out = (float*)d_out;

    __half *Aext = nullptr, *Bext = nullptr, *Wr = nullptr;
    cudaGetSymbolAddress((void**)&Aext, g_Aext);
    cudaGetSymbolAddress((void**)&Bext, g_Bext);
    cudaGetSymbolAddress((void**)&Wr,   g_Wr);

    static bool init_done = false;
    static cudaStream_t s1, s2;
    static cudaEvent_t evFork, evJoin1, evJoin2;
    if (!init_done) {
        cudaFuncSetAttribute(gemm_hmma_kernel,
                             cudaFuncAttributeMaxDynamicSharedMemorySize, GEMM_SMEM);
        cudaStreamCreateWithFlags(&s1, cudaStreamNonBlocking);
        cudaStreamCreateWithFlags(&s2, cudaStreamNonBlocking);
        cudaEventCreateWithFlags(&evFork,  cudaEventDisableTiming);
        cudaEventCreateWithFlags(&evJoin1, cudaEventDisableTiming);
        cudaEventCreateWithFlags(&evJoin2, cudaEventDisableTiming);
        init_done = true;
    }

    // fork
    cudaEventRecord(evFork, 0);
    cudaStreamWaitEvent(s1, evFork, 0);
    cudaStreamWaitEvent(s2, evFork, 0);

    // s1: B-side conversion (W fp16 + Bcat tail) — independent of X path
    {
        int total = OUT_F * (IN_F / 4) + OUT_F * 64;
        convert_w_bcat_kernel<<<(total + 255) / 256, 256, 0, s1>>>(base_w, Bm, Bext);
    }
    cudaEventRecord(evJoin1, s1);

    // s2: router weight pack — needed only by router_gemm
    wr_pack_kernel<<<(64 * IN_F / 4) / 256, 256, 0, s2>>>(A, rw, Wr);
    cudaEventRecord(evJoin2, s2);

    // main: X conversion, then router (needs Aext + Wr)
    convert_x_kernel<<<(M_TOK * IN_F / 4) / 256, 256>>>(x, Aext);
    cudaStreamWaitEvent(0, evJoin2, 0);
    router_gemm_kernel<<<M_TOK / 64, 128>>>(Aext, Wr, Aext);

    // join B-side, then fused GEMM
    cudaStreamWaitEvent(0, evJoin1, 0);
    dim3 grid(OUT_F / BNg, M_TOK / BMg);   // (16, 64) = 1024 CTAs
    gemm_hmma_kernel<<<grid, 256, GEMM_SMEM>>>(Aext, Bext, base_b, out);
}